// round 7
// baseline (speedup 1.0000x reference)
#include <cuda_runtime.h>

#define BB   4
#define CC   256
#define HH   56
#define WWD  56
#define HWP  3136        // 56*56
#define CR   64
#define GG   16
#define KW   7
#define GK   784         // G*K*K
#define EPSV 1e-5f

typedef unsigned long long ull;

// Scratch (no allocations allowed; static device global)
__device__ float g_w[(size_t)BB * GK * HWP];   // 39.3 MB

// ---- packed fp32 helpers (Blackwell f32x2) --------------------------------
__device__ __forceinline__ void upk2(ull p, float& lo, float& hi) {
    asm("mov.b64 {%0, %1}, %2;" : "=f"(lo), "=f"(hi) : "l"(p));
}
__device__ __forceinline__ ull ffma2(ull a, ull b, ull c) {
    ull d;
    asm("fma.rn.f32x2 %0, %1, %2, %3;" : "=l"(d) : "l"(a), "l"(b), "l"(c));
    return d;
}

// ---------------------------------------------------------------------------
// Fused kernel-generation. Block = 32 pixels, 128 threads, 392 blocks.
// Stage 1: t = relu(BN(W1@x+b1)) -> Ts_dup (pixels duplicated for f32x2).
// Stage 2: w = W2@t + b2 -> g_w, streamed in 7 chunks of 112 n.
//
// Packed-operand scheme (no pack movs): a-operand read as LDS.64 from
// duplicated pixels => (a,a); w-operand read as LDS.64/128 of contiguous
// outputs => (w_n, w_{n+1}).  All FFMA2.
// ---------------------------------------------------------------------------
#define TS_STRIDE  64      // floats, Ts_dup[64][64]
#define W1S_STRIDE 68      // floats, W1s[64][68]  (272B = 17*16 aligned)
#define W2S_STRIDE 116     // floats, W2s[64][116] (464B = 29*16 aligned)
#define GEN_SMEM_FLOATS (64*TS_STRIDE + 64*TS_STRIDE + 64*W1S_STRIDE)  // Ts + max(U)
#define GEN_SMEM_BYTES  (GEN_SMEM_FLOATS * 4)   // 50176 B

__global__ __launch_bounds__(128) void gen_tw_kernel(
    const float* __restrict__ x,  const float* __restrict__ W1,
    const float* __restrict__ b1, const float* __restrict__ gamma,
    const float* __restrict__ beta, const float* __restrict__ mean,
    const float* __restrict__ var,  const float* __restrict__ W2,
    const float* __restrict__ b2)
{
    extern __shared__ float sm[];
    float* Ts_dup = sm;                       // [64][TS_STRIDE]
    float* Ubase  = sm + 64 * TS_STRIDE;      // union region
    float* Xs_dup = Ubase;                    // s1: [64][TS_STRIDE]
    float* W1s    = Ubase + 64 * TS_STRIDE;   // s1: [64][W1S_STRIDE]
    float* W2s    = Ubase;                    // s2: [64][W2S_STRIDE]

    const int tid = threadIdx.x;
    const int m0  = blockIdx.x * 32;
    const int b   = m0 / HWP;
    const int p0  = m0 % HWP;         // 3136 % 32 == 0
    const int pxg = tid & 7;          // pixel quad id (4 px each)
    const int grp = tid >> 3;         // 0..15

    // ================= stage 1: 32px x 64out, K=256 =================
    // thread: 4 px x 4 outputs (o = 4*grp .. +3)
    ull acc1[4][2] = {};              // [px][o-pair]

    for (int c0 = 0; c0 < CC; c0 += 64) {
        // Xs_dup[k][2*px] = Xs_dup[k][2*px+1] = x value
        {
            const int lp = tid & 31;
            #pragma unroll
            for (int r = tid >> 5; r < 64; r += 4) {
                float v = x[((size_t)b * CC + c0 + r) * HWP + p0 + lp];
                Xs_dup[r * TS_STRIDE + 2 * lp]     = v;
                Xs_dup[r * TS_STRIDE + 2 * lp + 1] = v;
            }
        }
        // W1s[k][o] = W1[o][c0+k]
        {
            const int kq = tid & 15;
            #pragma unroll
            for (int o = tid >> 4; o < 64; o += 8) {
                float4 v = *(const float4*)&W1[o * CC + c0 + 4 * kq];
                W1s[(4 * kq + 0) * W1S_STRIDE + o] = v.x;
                W1s[(4 * kq + 1) * W1S_STRIDE + o] = v.y;
                W1s[(4 * kq + 2) * W1S_STRIDE + o] = v.z;
                W1s[(4 * kq + 3) * W1S_STRIDE + o] = v.w;
            }
        }
        __syncthreads();

        #pragma unroll 8
        for (int k = 0; k < 64; k++) {
            ull a[4];
            #pragma unroll
            for (int i = 0; i < 4; i++)
                a[i] = *(const ull*)&Xs_dup[k * TS_STRIDE + 2 * (4 * pxg + i)];
            ull2_t: ;
            ulonglong2 w2 = *(const ulonglong2*)&W1s[k * W1S_STRIDE + 4 * grp];
            #pragma unroll
            for (int i = 0; i < 4; i++) {
                acc1[i][0] = ffma2(a[i], w2.x, acc1[i][0]);
                acc1[i][1] = ffma2(a[i], w2.y, acc1[i][1]);
            }
        }
        __syncthreads();
    }

    // BN + ReLU epilogue -> Ts_dup[o][2*px] duplicated
    #pragma unroll
    for (int j = 0; j < 2; j++) {
        const int o0 = 4 * grp + 2 * j;
        const float sc0 = gamma[o0] * rsqrtf(var[o0] + EPSV);
        const float sh0 = beta[o0] - mean[o0] * sc0;
        const float bv0 = b1[o0];
        const float sc1 = gamma[o0 + 1] * rsqrtf(var[o0 + 1] + EPSV);
        const float sh1 = beta[o0 + 1] - mean[o0 + 1] * sc1;
        const float bv1 = b1[o0 + 1];
        #pragma unroll
        for (int i = 0; i < 4; i++) {
            float ve, vo;
            upk2(acc1[i][j], ve, vo);
            float t0 = fmaxf((ve + bv0) * sc0 + sh0, 0.f);
            float t1 = fmaxf((vo + bv1) * sc1 + sh1, 0.f);
            const int px = 4 * pxg + i;
            Ts_dup[o0 * TS_STRIDE + 2 * px]           = t0;
            Ts_dup[o0 * TS_STRIDE + 2 * px + 1]       = t0;
            Ts_dup[(o0 + 1) * TS_STRIDE + 2 * px]     = t1;
            Ts_dup[(o0 + 1) * TS_STRIDE + 2 * px + 1] = t1;
        }
    }

    // ================= stage 2: 32px x 784n, K=64, 7 chunks of 112 =========
    const int  ng     = grp;            // 0..15, only 0..13 active
    const bool active = (ng < 14);

    for (int n0 = 0; n0 < GK; n0 += 112) {
        __syncthreads();                // protect union region (prev readers)
        // W2s[k][n] = W2[n0+n][k]
        {
            const int kq = tid & 15;
            #pragma unroll
            for (int n = tid >> 4; n < 112; n += 8) {
                float4 v = *(const float4*)&W2[(n0 + n) * CR + 4 * kq];
                W2s[(4 * kq + 0) * W2S_STRIDE + n] = v.x;
                W2s[(4 * kq + 1) * W2S_STRIDE + n] = v.y;
                W2s[(4 * kq + 2) * W2S_STRIDE + n] = v.z;
                W2s[(4 * kq + 3) * W2S_STRIDE + n] = v.w;
            }
        }
        __syncthreads();

        if (active) {
            ull acc2[4][4] = {};        // [px][n-pair], n = 8*ng + 2j (+1)

            #pragma unroll 8
            for (int k = 0; k < 64; k++) {
                ull a[4];
                #pragma unroll
                for (int i = 0; i < 4; i++)
                    a[i] = *(const ull*)&Ts_dup[k * TS_STRIDE + 2 * (4 * pxg + i)];
                ulonglong2 wA = *(const ulonglong2*)&W2s[k * W2S_STRIDE + 8 * ng];
                ulonglong2 wB = *(const ulonglong2*)&W2s[k * W2S_STRIDE + 8 * ng + 4];
                #pragma unroll
                for (int i = 0; i < 4; i++) {
                    acc2[i][0] = ffma2(a[i], wA.x, acc2[i][0]);
                    acc2[i][1] = ffma2(a[i], wA.y, acc2[i][1]);
                    acc2[i][2] = ffma2(a[i], wB.x, acc2[i][2]);
                    acc2[i][3] = ffma2(a[i], wB.y, acc2[i][3]);
                }
            }

            // epilogue: vectorize over px (coalesced float4 stores)
            float vv[4][8];
            #pragma unroll
            for (int i = 0; i < 4; i++)
                #pragma unroll
                for (int j = 0; j < 4; j++)
                    upk2(acc2[i][j], vv[i][2 * j], vv[i][2 * j + 1]);
            #pragma unroll
            for (int nn = 0; nn < 8; nn++) {
                const int n = n0 + 8 * ng + nn;
                const float bv = b2[n];
                float4 o4 = make_float4(vv[0][nn] + bv, vv[1][nn] + bv,
                                        vv[2][nn] + bv, vv[3][nn] + bv);
                *(float4*)&g_w[((size_t)b * GK + n) * HWP + p0 + 4 * pxg] = o4;
            }
        }
    }
}

// ---------------------------------------------------------------------------
// Involution. Block = (2-row strip, g, b), 448 threads = 16 ch x 2 rows x 14
// pixel quads. w staged in smem once per 16 channels; x halo staged in smem.
// Thread = 1 channel x 4 px  (xr[10] only -> no spills).
// Channel in LOW lane bits so w-loads broadcast within the warp.
// ---------------------------------------------------------------------------
#define XCH_STRIDE 514                       // floats per channel (bank-spread)
#define XS_FLOATS  (15 * XCH_STRIDE + 512)   // 8222 -> round up
#define WS_FLOATS  (49 * 112)                // 5488
#define INV_SMEM_BYTES ((XS_FLOATS + 2 + WS_FLOATS) * 4)   // 54,848 B

__global__ __launch_bounds__(448) void inv_kernel(
    const float* __restrict__ x, float* __restrict__ out)
{
    extern __shared__ float sm[];
    float* xs = sm;                    // [16 ch][8 rows][64 cols], stride 514
    float* ws = sm + XS_FLOATS + 2;    // [49 tap][2 rows * 56 cols]

    const int tid = threadIdx.x;
    const int h0  = blockIdx.x * 2;
    const int g   = blockIdx.y;
    const int b   = blockIdx.z;

    // ---- stage x halo: rows h0-3 .. h0+4, cols -3 .. 60 (stored 0..63) ----
    const float* xg = x + ((size_t)b * CC + g * 16) * HWP;
    for (int idx = tid; idx < 16 * 512; idx += 448) {
        const int ch  = idx >> 9;
        const int rem = idx & 511;
        const int row = rem >> 6;
        const int col = rem & 63;
        const int hh  = h0 - 3 + row;
        const int wc  = col - 3;
        float v = 0.f;
        if (hh >= 0 && hh < HH && wc >= 0 && wc < WWD)
            v = xg[(size_t)ch * HWP + hh * WWD + wc];
        xs[ch * XCH_STRIDE + row * 64 + col] = v;
    }
    // ---- stage w: 49 taps x (2 rows x 56 cols) ----
    const float* wg = g_w + ((size_t)b * GK + g * 49) * HWP + h0 * WWD;
    for (int idx = tid; idx < WS_FLOATS; idx += 448) {
        const int tap = idx / 112;
        const int rem = idx - tap * 112;
        ws[idx] = wg[(size_t)tap * HWP + rem];
    }
    __syncthreads();

    const int cc   = tid & 15;          // channel (low bits -> w broadcast)
    const int pq   = tid >> 4;          // 0..27
    const int r    = pq / 14;           // row within strip (0..1)
    const int col0 = 4 * (pq % 14);     // pixel quad start

    const float* xch = xs + cc * XCH_STRIDE;
    float acc0 = 0.f, acc1 = 0.f, acc2 = 0.f, acc3 = 0.f;

    #pragma unroll
    for (int i = 0; i < KW; i++) {
        float xr[10];
        const float* xrow = xch + (r + i) * 64 + col0;
        #pragma unroll
        for (int d = 0; d < 10; d++) xr[d] = xrow[d];
        #pragma unroll
        for (int j = 0; j < KW; j++) {
            float4 wv = *(const float4*)&ws[(i * 7 + j) * 112 + r * 56 + col0];
            acc0 = fmaf(xr[j + 0], wv.x, acc0);
            acc1 = fmaf(xr[j + 1], wv.y, acc1);
            acc2 = fmaf(xr[j + 2], wv.z, acc2);
            acc3 = fmaf(xr[j + 3], wv.w, acc3);
        }
    }

    float4 o4 = make_float4(acc0, acc1, acc2, acc3);
    *(float4*)&out[((size_t)b * CC + g * 16 + cc) * HWP + (h0 + r) * WWD + col0] = o4;
}

// ---------------------------------------------------------------------------
extern "C" void kernel_launch(void* const* d_in, const int* in_sizes, int n_in,
                              void* d_out, int out_size)
{
    const float* x     = (const float*)d_in[0];
    const float* W1    = (const float*)d_in[1];
    const float* b1    = (const float*)d_in[2];
    const float* gamma = (const float*)d_in[3];
    const float* beta  = (const float*)d_in[4];
    const float* mean  = (const float*)d_in[5];
    const float* var   = (const float*)d_in[6];
    const float* W2    = (const float*)d_in[7];
    const float* b2    = (const float*)d_in[8];
    float* out = (float*)d_out;

    static int smem_set = 0;
    if (!smem_set) {
        cudaFuncSetAttribute(gen_tw_kernel,
                             cudaFuncAttributeMaxDynamicSharedMemorySize,
                             GEN_SMEM_BYTES);
        cudaFuncSetAttribute(inv_kernel,
                             cudaFuncAttributeMaxDynamicSharedMemorySize,
                             INV_SMEM_BYTES);
        smem_set = 1;
    }

    gen_tw_kernel<<<392, 128, GEN_SMEM_BYTES>>>(x, W1, b1, gamma, beta, mean,
                                                var, W2, b2);
    inv_kernel<<<dim3(28, GG, BB), 448, INV_SMEM_BYTES>>>(x, out);
}

// round 9
// speedup vs baseline: 1.2502x; 1.2502x over previous
#include <cuda_runtime.h>

#define BB   4
#define CC   256
#define HH   56
#define WWD  56
#define HWP  3136        // 56*56
#define CR   64
#define GG   16
#define KW   7
#define GK   784         // G*K*K
#define EPSV 1e-5f

typedef unsigned long long ull;

// Scratch (no allocations allowed; static device global)
__device__ float g_w[(size_t)BB * GK * HWP];   // 39.3 MB

// ---- packed fp32 helpers (Blackwell f32x2) --------------------------------
__device__ __forceinline__ void upk2(ull p, float& lo, float& hi) {
    asm("mov.b64 {%0, %1}, %2;" : "=f"(lo), "=f"(hi) : "l"(p));
}
__device__ __forceinline__ ull ffma2(ull a, ull b, ull c) {
    ull d;
    asm("fma.rn.f32x2 %0, %1, %2, %3;" : "=l"(d) : "l"(a), "l"(b), "l"(c));
    return d;
}

// pixel placement inside dup'd rows: px -> word offset (conflict-free units)
__device__ __forceinline__ int fpx(int px) {
    const int q = px >> 2;
    return 8 * q + 4 * (q >> 2) + 2 * (px & 3);
}

// ---------------------------------------------------------------------------
// Fused kernel generation.  Block = 32 pixels, 128 threads, 392 blocks
// (one full wave at 4 blocks/SM).
// Stage 1: t = relu(BN(W1@x+b1)) -> Ts (pixels duplicated, swizzled).
// Stage 2: w = W2@t + b2 -> g_w in 7 chunks of 112 n.
// a-operand: LDS.128 of dup'd pixels => two (x,x) pairs.
// w-operand: LDS.128 of transposed weights => two (w_n, w_{n+1}) pairs.
// Weight rows are XOR-swizzled at 16B-unit granularity so the k-scalar
// transposed staging stores are ~conflict-free and loads are conflict-free.
// ---------------------------------------------------------------------------
#define TS_STR 72
#define W1_STR 68
#define W2_STR 132
#define SM_TS  0
#define SM_U   (64 * TS_STR)               // 4608
#define SM_XS  SM_U
#define SM_W1  (SM_U + 64 * TS_STR)        // 9216
#define SM_W2  SM_U
#define GEN_SMEM_WORDS (SM_U + 64 * TS_STR + 64 * W1_STR)   // 13568
#define GEN_SMEM_BYTES (GEN_SMEM_WORDS * 4)                 // 54272

__global__ __launch_bounds__(128, 4) void gen_tw_kernel(
    const float* __restrict__ x,  const float* __restrict__ W1,
    const float* __restrict__ b1, const float* __restrict__ gamma,
    const float* __restrict__ beta, const float* __restrict__ mean,
    const float* __restrict__ var,  const float* __restrict__ W2,
    const float* __restrict__ b2)
{
    extern __shared__ float sm[];

    const int tid = threadIdx.x;
    const int m0  = blockIdx.x * 32;
    const int b   = m0 / HWP;
    const int p0  = m0 % HWP;          // 3136 % 32 == 0
    const int pxg = tid & 7;           // pixel quad (4 px)
    const int grp = tid >> 3;          // 0..15
    const int Ab  = 8 * pxg + 4 * (pxg >> 2);   // a-operand unit base

    // ================= stage 1: 32px x 64out, K=256 ====================
    ull acc1[4][2] = {};               // [px][o-pair]

    for (int c0 = 0; c0 < CC; c0 += 64) {
        {   // stage X (dup'd pixels)
            const int lp  = tid & 31;
            const int off = fpx(lp);
            #pragma unroll
            for (int r = tid >> 5; r < 64; r += 4) {
                float v = x[((size_t)b * CC + c0 + r) * HWP + p0 + lp];
                *(float2*)&sm[SM_XS + r * TS_STR + off] = make_float2(v, v);
            }
        }
        {   // stage W1 transposed, swizzled
            const int k = tid & 63;
            const int s = (k >> 2) & 15;
            #pragma unroll
            for (int o = tid >> 6; o < 64; o += 2)
                sm[SM_W1 + k * W1_STR + 4 * ((o >> 2) ^ s) + (o & 3)] =
                    W1[o * CC + c0 + k];
        }
        __syncthreads();

        #pragma unroll 8
        for (int k = 0; k < 64; k++) {
            ulonglong2 aA = *(const ulonglong2*)&sm[SM_XS + k * TS_STR + Ab];
            ulonglong2 aB = *(const ulonglong2*)&sm[SM_XS + k * TS_STR + Ab + 4];
            ulonglong2 wv = *(const ulonglong2*)
                &sm[SM_W1 + k * W1_STR + 4 * (grp ^ ((k >> 2) & 15))];
            acc1[0][0] = ffma2(aA.x, wv.x, acc1[0][0]);
            acc1[0][1] = ffma2(aA.x, wv.y, acc1[0][1]);
            acc1[1][0] = ffma2(aA.y, wv.x, acc1[1][0]);
            acc1[1][1] = ffma2(aA.y, wv.y, acc1[1][1]);
            acc1[2][0] = ffma2(aB.x, wv.x, acc1[2][0]);
            acc1[2][1] = ffma2(aB.x, wv.y, acc1[2][1]);
            acc1[3][0] = ffma2(aB.y, wv.x, acc1[3][0]);
            acc1[3][1] = ffma2(aB.y, wv.y, acc1[3][1]);
        }
        __syncthreads();
    }

    // BN + ReLU epilogue -> Ts (dup'd, swizzled)
    #pragma unroll
    for (int j = 0; j < 2; j++) {
        const int o0 = 4 * grp + 2 * j;
        const float sc0 = gamma[o0] * rsqrtf(var[o0] + EPSV);
        const float sh0 = beta[o0] - mean[o0] * sc0;
        const float bv0 = b1[o0];
        const float sc1 = gamma[o0 + 1] * rsqrtf(var[o0 + 1] + EPSV);
        const float sh1 = beta[o0 + 1] - mean[o0 + 1] * sc1;
        const float bv1 = b1[o0 + 1];
        #pragma unroll
        for (int i = 0; i < 4; i++) {
            float ve, vo;
            upk2(acc1[i][j], ve, vo);
            const float t0 = fmaxf((ve + bv0) * sc0 + sh0, 0.f);
            const float t1 = fmaxf((vo + bv1) * sc1 + sh1, 0.f);
            const int off = fpx(4 * pxg + i);
            *(float2*)&sm[SM_TS + o0 * TS_STR + off]       = make_float2(t0, t0);
            *(float2*)&sm[SM_TS + (o0 + 1) * TS_STR + off] = make_float2(t1, t1);
        }
    }
    __syncthreads();

    // ================= stage 2: 32px x 784n, K=64 ======================
    const int  ng     = grp;
    const bool active = (ng < 14);

    for (int n0 = 0; n0 < GK; n0 += 112) {
        {   // stage W2 transposed, swizzled
            const int k = tid & 63;
            const int s = (k >> 2) & 7;
            #pragma unroll
            for (int n = tid >> 6; n < 112; n += 2)
                sm[SM_W2 + k * W2_STR + 4 * ((n >> 2) ^ s) + (n & 3)] =
                    W2[(n0 + n) * CR + k];
        }
        __syncthreads();

        if (active) {
            ull acc2[4][4] = {};       // [px][n-pair]

            #pragma unroll 8
            for (int k = 0; k < 64; k++) {
                ulonglong2 aA = *(const ulonglong2*)&sm[SM_TS + k * TS_STR + Ab];
                ulonglong2 aB = *(const ulonglong2*)&sm[SM_TS + k * TS_STR + Ab + 4];
                const int s2 = (k >> 2) & 7;
                ulonglong2 wA = *(const ulonglong2*)
                    &sm[SM_W2 + k * W2_STR + 4 * ((2 * ng) ^ s2)];
                ulonglong2 wB = *(const ulonglong2*)
                    &sm[SM_W2 + k * W2_STR + 4 * ((2 * ng + 1) ^ s2)];
                ull a[4] = {aA.x, aA.y, aB.x, aB.y};
                #pragma unroll
                for (int i = 0; i < 4; i++) {
                    acc2[i][0] = ffma2(a[i], wA.x, acc2[i][0]);
                    acc2[i][1] = ffma2(a[i], wA.y, acc2[i][1]);
                    acc2[i][2] = ffma2(a[i], wB.x, acc2[i][2]);
                    acc2[i][3] = ffma2(a[i], wB.y, acc2[i][3]);
                }
            }

            float vv[4][8];
            #pragma unroll
            for (int i = 0; i < 4; i++)
                #pragma unroll
                for (int j = 0; j < 4; j++)
                    upk2(acc2[i][j], vv[i][2 * j], vv[i][2 * j + 1]);
            #pragma unroll
            for (int nn = 0; nn < 8; nn++) {
                const int n = n0 + 8 * ng + nn;
                const float bv = b2[n];
                float4 o4 = make_float4(vv[0][nn] + bv, vv[1][nn] + bv,
                                        vv[2][nn] + bv, vv[3][nn] + bv);
                *(float4*)&g_w[((size_t)b * GK + n) * HWP + p0 + 4 * pxg] = o4;
            }
        }
        __syncthreads();
    }
}

// ---------------------------------------------------------------------------
// Involution, channel-pair FFMA2.
// Block = (2-row strip, g, b), 224 threads = 8 ch-pairs x 2 rows x 14 quads.
// x staged interleaved (ch_even, ch_odd) pairs  -> a-operand natural LDS.128.
// w staged duplicated (w, w)                    -> b-operand natural LDS.128.
// Thread = 1 ch-pair x 4 px = 8 outputs.
// ---------------------------------------------------------------------------
#define CPS        1028                       // cp stride (mod 32 == 4)
#define XS_WORDS   (8 * CPS)                  // 8224
#define WS_WORDS   (49 * 224)                 // 10976
#define INV_SMEM_BYTES ((XS_WORDS + WS_WORDS) * 4)   // 76800

__global__ __launch_bounds__(224, 2) void inv_kernel(
    const float* __restrict__ x, float* __restrict__ out)
{
    extern __shared__ float sm[];
    float* xs = sm;               // [8 cp][8 rows][64 cols x 2 interleaved]
    float* ws = sm + XS_WORDS;    // [49 tap][2 rows][56 px x 2 dup]

    const int tid = threadIdx.x;
    const int h0  = blockIdx.x * 2;
    const int g   = blockIdx.y;
    const int b   = blockIdx.z;

    // ---- stage x: rows h0-3..h0+4, cols -3..60, interleaved ch pairs ----
    const float* xg = x + ((size_t)b * CC + g * 16) * HWP;
    for (int idx = tid; idx < 16 * 512; idx += 224) {
        const int ch  = idx >> 9;
        const int row = (idx >> 6) & 7;
        const int col = idx & 63;
        const int hh  = h0 - 3 + row;
        const int wc  = col - 3;
        float v = 0.f;
        if (hh >= 0 && hh < HH && wc >= 0 && wc < WWD)
            v = xg[(size_t)ch * HWP + hh * WWD + wc];
        xs[(ch >> 1) * CPS + row * 128 + 2 * col + (ch & 1)] = v;
    }
    // ---- stage w duplicated ----
    {
        const int half = tid / 112;          // 0..1
        const int s    = tid - 112 * half;   // 0..111 = r*56 + col
        const float* wg = g_w + ((size_t)b * GK + g * 49) * HWP + h0 * WWD;
        for (int tap = half; tap < 49; tap += 2) {
            float v = wg[(size_t)tap * HWP + s];
            *(float2*)&ws[tap * 224 + 2 * s] = make_float2(v, v);
        }
    }
    __syncthreads();

    const int cp   = tid & 7;
    const int pxq  = tid >> 3;          // 0..27
    const int r    = pxq / 14;
    const int col0 = 4 * (pxq - 14 * r);

    const float* xb = xs + cp * CPS + r * 128 + 2 * col0;
    const float* wb = ws + r * 112 + 2 * col0;

    ull acc[4] = {};                    // [px], packed (ch_even, ch_odd)

    #pragma unroll
    for (int i = 0; i < KW; i++) {
        ull xp[10];
        #pragma unroll
        for (int d = 0; d < 10; d += 2) {
            ulonglong2 v = *(const ulonglong2*)(xb + i * 128 + 2 * d);
            xp[d] = v.x;  xp[d + 1] = v.y;
        }
        #pragma unroll
        for (int j = 0; j < KW; j++) {
            const float* wt = wb + (i * 7 + j) * 224;
            ulonglong2 wA = *(const ulonglong2*)(wt);       // px 0,1
            ulonglong2 wB = *(const ulonglong2*)(wt + 4);   // px 2,3
            acc[0] = ffma2(xp[j + 0], wA.x, acc[0]);
            acc[1] = ffma2(xp[j + 1], wA.y, acc[1]);
            acc[2] = ffma2(xp[j + 2], wB.x, acc[2]);
            acc[3] = ffma2(xp[j + 3], wB.y, acc[3]);
        }
    }

    float e0, o0, e1, o1, e2, o2, e3, o3;
    upk2(acc[0], e0, o0); upk2(acc[1], e1, o1);
    upk2(acc[2], e2, o2); upk2(acc[3], e3, o3);
    const size_t obase = ((size_t)b * CC + g * 16 + 2 * cp) * HWP
                       + (h0 + r) * WWD + col0;
    *(float4*)&out[obase]       = make_float4(e0, e1, e2, e3);
    *(float4*)&out[obase + HWP] = make_float4(o0, o1, o2, o3);
}

// ---------------------------------------------------------------------------
extern "C" void kernel_launch(void* const* d_in, const int* in_sizes, int n_in,
                              void* d_out, int out_size)
{
    const float* x     = (const float*)d_in[0];
    const float* W1    = (const float*)d_in[1];
    const float* b1    = (const float*)d_in[2];
    const float* gamma = (const float*)d_in[3];
    const float* beta  = (const float*)d_in[4];
    const float* mean  = (const float*)d_in[5];
    const float* var   = (const float*)d_in[6];
    const float* W2    = (const float*)d_in[7];
    const float* b2    = (const float*)d_in[8];
    float* out = (float*)d_out;

    static int smem_set = 0;
    if (!smem_set) {
        cudaFuncSetAttribute(gen_tw_kernel,
                             cudaFuncAttributeMaxDynamicSharedMemorySize,
                             GEN_SMEM_BYTES);
        cudaFuncSetAttribute(inv_kernel,
                             cudaFuncAttributeMaxDynamicSharedMemorySize,
                             INV_SMEM_BYTES);
        smem_set = 1;
    }

    gen_tw_kernel<<<392, 128, GEN_SMEM_BYTES>>>(x, W1, b1, gamma, beta, mean,
                                                var, W2, b2);
    inv_kernel<<<dim3(28, GG, BB), 224, INV_SMEM_BYTES>>>(x, out);
}